// round 1
// baseline (speedup 1.0000x reference)
#include <cuda_runtime.h>
#include <mma.h>
#include <math.h>

// URNNCell: out = modrelu( complex(inputs@W^T) + D3·R2·IFFT·D2·P·R1·FFT·D1·state_c )
// B=8192, N_IN=1024, N=2048 (complex), 2N=4096.

#define N_FFT   2048
#define HALF_N  1024
#define BATCH   8192
#define NIN     1024
#define TWO_N   4096

using namespace nvcuda;

// ---------------- device scratch (static: no allocations allowed) ----------------
__device__ float g_inputs_mul[(size_t)BATCH * TWO_N];   // GEMM output (re | im halves)
__device__ float g_c1[N_FFT], g_s1[N_FFT];
__device__ float g_c2[N_FFT], g_s2[N_FFT];
__device__ float g_c3[N_FFT], g_s3[N_FFT];
__device__ float g_fac1, g_fac2;                        // 2 / ||v||^2

// ---------------- setup: cos/sin tables for diag phases + reflection norms -------
__global__ void setup_kernel(const float* __restrict__ d1,
                             const float* __restrict__ r1re, const float* __restrict__ r1im,
                             const float* __restrict__ d2,
                             const float* __restrict__ r2re, const float* __restrict__ r2im,
                             const float* __restrict__ d3) {
    int tid = threadIdx.x;
    float p1 = 0.f, p2 = 0.f;
    for (int i = tid; i < N_FFT; i += blockDim.x) {
        float s, c;
        sincosf(d1[i], &s, &c); g_c1[i] = c; g_s1[i] = s;
        sincosf(d2[i], &s, &c); g_c2[i] = c; g_s2[i] = s;
        sincosf(d3[i], &s, &c); g_c3[i] = c; g_s3[i] = s;
        p1 += r1re[i]*r1re[i] + r1im[i]*r1im[i];
        p2 += r2re[i]*r2re[i] + r2im[i]*r2im[i];
    }
    __shared__ float sh1[32], sh2[32];
    unsigned m = 0xffffffffu;
    for (int o = 16; o; o >>= 1) { p1 += __shfl_down_sync(m, p1, o); p2 += __shfl_down_sync(m, p2, o); }
    int w = tid >> 5, l = tid & 31;
    if (l == 0) { sh1[w] = p1; sh2[w] = p2; }
    __syncthreads();
    if (w == 0) {
        int nw = blockDim.x >> 5;
        p1 = (l < nw) ? sh1[l] : 0.f;
        p2 = (l < nw) ? sh2[l] : 0.f;
        for (int o = 16; o; o >>= 1) { p1 += __shfl_down_sync(m, p1, o); p2 += __shfl_down_sync(m, p2, o); }
        if (l == 0) { g_fac1 = 2.f / p1; g_fac2 = 2.f / p2; }
    }
}

// ---------------- GEMM: C[b,m] = sum_k inputs[b,k] * w_ih[m,k]  (tf32 wmma) ------
#define BM 128
#define BN 128
#define BK 32
#define LDS_A 36   // padded leading dim (multiple of 4 elems)

__global__ __launch_bounds__(256) void gemm_tf32(const float* __restrict__ A,
                                                 const float* __restrict__ W) {
    __shared__ float As[BM][LDS_A];
    __shared__ float Bs[BN][LDS_A];
    int tid  = threadIdx.x;
    int warp = tid >> 5;
    int wm = warp >> 1;   // 0..3 -> 32-row slab
    int wn = warp & 1;    // 0..1 -> 64-col slab
    int bm = blockIdx.y, bn = blockIdx.x;

    const float* Ag = A + (size_t)bm * BM * NIN;
    const float* Wg = W + (size_t)bn * BN * NIN;

    wmma::fragment<wmma::accumulator, 16, 16, 8, float> acc[2][4];
    #pragma unroll
    for (int i = 0; i < 2; i++)
        #pragma unroll
        for (int j = 0; j < 4; j++) wmma::fill_fragment(acc[i][j], 0.f);

    for (int k0 = 0; k0 < NIN; k0 += BK) {
        // 128 rows x 32 cols per tile = 1024 float4; 256 threads x 4 each
        #pragma unroll
        for (int r = 0; r < 4; r++) {
            int idx = tid + 256 * r;
            int row = idx >> 3, c4 = idx & 7;
            float4 va = *(const float4*)(Ag + (size_t)row * NIN + k0 + c4 * 4);
            *(float4*)(&As[row][c4 * 4]) = va;
            float4 vb = *(const float4*)(Wg + (size_t)row * NIN + k0 + c4 * 4);
            *(float4*)(&Bs[row][c4 * 4]) = vb;
        }
        __syncthreads();
        #pragma unroll
        for (int ks = 0; ks < BK; ks += 8) {
            wmma::fragment<wmma::matrix_a, 16, 16, 8, wmma::precision::tf32, wmma::row_major> af[2];
            wmma::fragment<wmma::matrix_b, 16, 16, 8, wmma::precision::tf32, wmma::col_major> bf[4];
            #pragma unroll
            for (int i = 0; i < 2; i++) {
                wmma::load_matrix_sync(af[i], &As[wm * 32 + i * 16][ks], LDS_A);
                #pragma unroll
                for (int t = 0; t < af[i].num_elements; t++)
                    af[i].x[t] = wmma::__float_to_tf32(af[i].x[t]);
            }
            #pragma unroll
            for (int j = 0; j < 4; j++) {
                wmma::load_matrix_sync(bf[j], &Bs[wn * 64 + j * 16][ks], LDS_A);
                #pragma unroll
                for (int t = 0; t < bf[j].num_elements; t++)
                    bf[j].x[t] = wmma::__float_to_tf32(bf[j].x[t]);
            }
            #pragma unroll
            for (int i = 0; i < 2; i++)
                #pragma unroll
                for (int j = 0; j < 4; j++)
                    wmma::mma_sync(acc[i][j], af[i], bf[j], acc[i][j]);
        }
        __syncthreads();
    }
    #pragma unroll
    for (int i = 0; i < 2; i++)
        #pragma unroll
        for (int j = 0; j < 4; j++) {
            float* cp = g_inputs_mul
                      + (size_t)(bm * BM + wm * 32 + i * 16) * TWO_N
                      + bn * BN + wn * 64 + j * 16;
            wmma::store_matrix_sync(cp, acc[i][j], TWO_N, wmma::mem_row_major);
        }
}

// ---------------- per-row complex pipeline -----------------------------------
__device__ __forceinline__ float2 cmul(float2 a, float2 b) {
    return make_float2(a.x * b.x - a.y * b.y, a.x * b.y + a.y * b.x);
}

// Stockham radix-2 autosort FFT over N_FFT points in shared memory (ping-pong).
// Forward table: tw[j] = e^{-2*pi*i*j/N}. INV conjugates (unnormalized inverse).
template <bool INV>
__device__ __forceinline__ void fft_stages(float2*& src, float2*& dst,
                                           const float2* __restrict__ tw, int tid) {
    for (int s = 1; s < N_FFT; s <<= 1) {
        for (int t = tid; t < HALF_N; t += 256) {
            int ps = t & ~(s - 1);           // p*s
            float2 a = src[t];
            float2 c = src[t + HALF_N];
            float2 w = tw[ps];
            if (INV) w.y = -w.y;
            float2 dif = make_float2(a.x - c.x, a.y - c.y);
            dst[t + ps]     = make_float2(a.x + c.x, a.y + c.y);
            dst[t + ps + s] = cmul(dif, w);
        }
        __syncthreads();
        float2* tmp = src; src = dst; dst = tmp;
    }
}

__global__ __launch_bounds__(256) void urnn_row_kernel(
    const float* __restrict__ state,
    const float* __restrict__ r1re, const float* __restrict__ r1im,
    const float* __restrict__ r2re, const float* __restrict__ r2im,
    const int*   __restrict__ perm,
    const float* __restrict__ bh,
    float* __restrict__ out) {
    __shared__ float2 bufA[N_FFT];
    __shared__ float2 bufB[N_FFT];
    __shared__ float2 tw[HALF_N];
    __shared__ float2 red[8];
    __shared__ float2 vz_sh;

    int tid = threadIdx.x;
    int b   = blockIdx.x;

    // twiddle table
    for (int i = tid; i < HALF_N; i += 256) {
        float s, c;
        sincosf(-6.283185307179586f * (float)i / (float)N_FFT, &s, &c);
        tw[i] = make_float2(c, s);
    }

    // load state row + diag1
    const float* st = state + (size_t)b * TWO_N;
    for (int i = tid; i < N_FFT; i += 256) {
        float re = st[i], im = st[i + N_FFT];
        float c = g_c1[i], s = g_s1[i];
        bufA[i] = make_float2(re * c - im * s, re * s + im * c);
    }
    __syncthreads();

    float2* src = bufA;
    float2* dst = bufB;

    // forward FFT
    fft_stages<false>(src, dst, tw, tid);

    // reflect 1: z -= (2/||v||^2 * <z, v>) * v
    {
        float2 p = make_float2(0.f, 0.f);
        for (int i = tid; i < N_FFT; i += 256) {
            float2 z = src[i];
            float vr = r1re[i], vi = r1im[i];
            p.x += z.x * vr + z.y * vi;     // z * conj(v)
            p.y += z.y * vr - z.x * vi;
        }
        unsigned m = 0xffffffffu;
        for (int o = 16; o; o >>= 1) { p.x += __shfl_down_sync(m, p.x, o); p.y += __shfl_down_sync(m, p.y, o); }
        if ((tid & 31) == 0) red[tid >> 5] = p;
        __syncthreads();
        if (tid < 32) {
            float2 q = (tid < 8) ? red[tid] : make_float2(0.f, 0.f);
            for (int o = 4; o; o >>= 1) { q.x += __shfl_down_sync(m, q.x, o); q.y += __shfl_down_sync(m, q.y, o); }
            if (tid == 0) vz_sh = q;
        }
        __syncthreads();
        float2 f = vz_sh;
        float fac = g_fac1;
        f.x *= fac; f.y *= fac;
        for (int i = tid; i < N_FFT; i += 256) {
            float vr = r1re[i], vi = r1im[i];
            float2 z = src[i];
            z.x -= f.x * vr - f.y * vi;
            z.y -= f.x * vi + f.y * vr;
            src[i] = z;
        }
        __syncthreads();
    }

    // permutation + diag2
    for (int i = tid; i < N_FFT; i += 256) {
        int j = perm[i];
        float2 z = src[j];
        dst[i] = cmul(z, make_float2(g_c2[i], g_s2[i]));
    }
    __syncthreads();
    { float2* t = src; src = dst; dst = t; }

    // inverse FFT (unnormalized; 1/N folded into final step)
    fft_stages<true>(src, dst, tw, tid);

    // reflect 2
    {
        float2 p = make_float2(0.f, 0.f);
        for (int i = tid; i < N_FFT; i += 256) {
            float2 z = src[i];
            float vr = r2re[i], vi = r2im[i];
            p.x += z.x * vr + z.y * vi;
            p.y += z.y * vr - z.x * vi;
        }
        unsigned m = 0xffffffffu;
        for (int o = 16; o; o >>= 1) { p.x += __shfl_down_sync(m, p.x, o); p.y += __shfl_down_sync(m, p.y, o); }
        if ((tid & 31) == 0) red[tid >> 5] = p;
        __syncthreads();
        if (tid < 32) {
            float2 q = (tid < 8) ? red[tid] : make_float2(0.f, 0.f);
            for (int o = 4; o; o >>= 1) { q.x += __shfl_down_sync(m, q.x, o); q.y += __shfl_down_sync(m, q.y, o); }
            if (tid == 0) vz_sh = q;
        }
        __syncthreads();
        float2 f = vz_sh;
        float fac = g_fac2;
        f.x *= fac; f.y *= fac;
        for (int i = tid; i < N_FFT; i += 256) {
            float vr = r2re[i], vi = r2im[i];
            float2 z = src[i];
            z.x -= f.x * vr - f.y * vi;
            z.y -= f.x * vi + f.y * vr;
            src[i] = z;
        }
        __syncthreads();
    }

    // diag3 * (1/N), add inputs_c, modReLU, write out
    const float* gin = g_inputs_mul + (size_t)b * TWO_N;
    float* ob = out + (size_t)b * TWO_N;
    const float invN = 1.f / (float)N_FFT;
    for (int i = tid; i < N_FFT; i += 256) {
        float2 z = cmul(src[i], make_float2(g_c3[i], g_s3[i]));
        float pre_r = gin[i]        + z.x * invN;
        float pre_i = gin[i + N_FFT] + z.y * invN;
        float nrm = sqrtf(pre_r * pre_r + pre_i * pre_i);
        float sc = fmaxf(nrm + bh[i], 0.f) / (nrm + 1e-6f);
        ob[i]          = pre_r * sc;
        ob[i + N_FFT]  = pre_i * sc;
    }
}

// ---------------- launch ------------------------------------------------------
extern "C" void kernel_launch(void* const* d_in, const int* in_sizes, int n_in,
                              void* d_out, int out_size) {
    const float* inputs = (const float*)d_in[0];
    const float* state  = (const float*)d_in[1];
    const float* w_ih   = (const float*)d_in[2];
    const float* b_h    = (const float*)d_in[3];
    const float* d1     = (const float*)d_in[4];
    const float* r1re   = (const float*)d_in[5];
    const float* r1im   = (const float*)d_in[6];
    const float* d2     = (const float*)d_in[7];
    const float* r2re   = (const float*)d_in[8];
    const float* r2im   = (const float*)d_in[9];
    const float* d3     = (const float*)d_in[10];
    const int*   perm   = (const int*)d_in[11];
    float* out = (float*)d_out;

    setup_kernel<<<1, 256>>>(d1, r1re, r1im, d2, r2re, r2im, d3);

    dim3 g(TWO_N / BN, BATCH / BM);   // (32, 64)
    gemm_tf32<<<g, 256>>>(inputs, w_ih);

    urnn_row_kernel<<<BATCH, 256>>>(state, r1re, r1im, r2re, r2im, perm, b_h, out);
}

// round 2
// speedup vs baseline: 1.1209x; 1.1209x over previous
#include <cuda_runtime.h>
#include <mma.h>
#include <math.h>

// URNNCell: out = modrelu( complex(inputs@W^T) + D3·R2·IFFT·D2·P·R1·FFT·D1·state_c )
// B=8192, N_IN=1024, N=2048 (complex), 2N=4096.

#define N_FFT   2048
#define BATCH   8192
#define NIN     1024
#define TWO_N   4096
#define SW(i)   ((i) + ((i) >> 5))       // smem skew: kills power-of-2 stride conflicts

using namespace nvcuda;

// ---------------- device scratch (no allocations allowed) ----------------
__device__ float  g_inputs_mul[(size_t)BATCH * TWO_N];
__device__ float2 g_d1cs[N_FFT], g_d2cs[N_FFT], g_d3cs[N_FFT];   // (cos, sin)
__device__ float2 g_tw[257];                                     // e^{-2pi i j/2048}, j<=256
__device__ float  g_fac1, g_fac2;                                // 2/||v||^2

// ---------------- setup ----------------
__global__ void setup_kernel(const float* __restrict__ d1,
                             const float* __restrict__ r1re, const float* __restrict__ r1im,
                             const float* __restrict__ d2,
                             const float* __restrict__ r2re, const float* __restrict__ r2im,
                             const float* __restrict__ d3) {
    int tid = threadIdx.x;               // 512 threads
    float p1 = 0.f, p2 = 0.f;
    for (int i = tid; i < N_FFT; i += blockDim.x) {
        float s, c;
        sincosf(d1[i], &s, &c); g_d1cs[i] = make_float2(c, s);
        sincosf(d2[i], &s, &c); g_d2cs[i] = make_float2(c, s);
        sincosf(d3[i], &s, &c); g_d3cs[i] = make_float2(c, s);
        p1 += r1re[i]*r1re[i] + r1im[i]*r1im[i];
        p2 += r2re[i]*r2re[i] + r2im[i]*r2im[i];
    }
    for (int i = tid; i < 257; i += blockDim.x) {
        float s, c;
        sincosf(-6.283185307179586f * (float)i / (float)N_FFT, &s, &c);
        g_tw[i] = make_float2(c, s);
    }
    __shared__ float sh1[16], sh2[16];
    unsigned m = 0xffffffffu;
    for (int o = 16; o; o >>= 1) { p1 += __shfl_down_sync(m, p1, o); p2 += __shfl_down_sync(m, p2, o); }
    int w = tid >> 5, l = tid & 31;
    if (l == 0) { sh1[w] = p1; sh2[w] = p2; }
    __syncthreads();
    if (w == 0) {
        int nw = blockDim.x >> 5;
        p1 = (l < nw) ? sh1[l] : 0.f;
        p2 = (l < nw) ? sh2[l] : 0.f;
        for (int o = 8; o; o >>= 1) { p1 += __shfl_down_sync(m, p1, o); p2 += __shfl_down_sync(m, p2, o); }
        if (l == 0) { g_fac1 = 2.f / p1; g_fac2 = 2.f / p2; }
    }
}

// ---------------- GEMM: C[b,m] = sum_k inputs[b,k] * w_ih[m,k]  (tf32 wmma) ------
#define BM 128
#define BN 128
#define BK 32
#define LDSA 36

__global__ __launch_bounds__(512) void gemm_tf32(const float* __restrict__ A,
                                                 const float* __restrict__ W) {
    __shared__ float As[BM][LDSA];
    __shared__ float Bs[BN][LDSA];
    int tid  = threadIdx.x;
    int warp = tid >> 5;
    int wm = warp >> 2;   // 0..3 -> 32-row slab
    int wn = warp & 3;    // 0..3 -> 32-col slab
    int bm = blockIdx.y, bn = blockIdx.x;

    const float* Ag = A + (size_t)bm * BM * NIN;
    const float* Wg = W + (size_t)bn * BN * NIN;

    wmma::fragment<wmma::accumulator, 16, 16, 8, float> acc[2][2];
    #pragma unroll
    for (int i = 0; i < 2; i++)
        #pragma unroll
        for (int j = 0; j < 2; j++) wmma::fill_fragment(acc[i][j], 0.f);

    int row[2], c4[2];
    #pragma unroll
    for (int r = 0; r < 2; r++) { int idx = tid + 512 * r; row[r] = idx >> 3; c4[r] = idx & 7; }

    float4 pa[2], pb[2];
    // prefetch tile 0
    #pragma unroll
    for (int r = 0; r < 2; r++) {
        pa[r] = *(const float4*)(Ag + (size_t)row[r] * NIN + c4[r] * 4);
        pb[r] = *(const float4*)(Wg + (size_t)row[r] * NIN + c4[r] * 4);
    }
    #pragma unroll
    for (int r = 0; r < 2; r++) {
        *(float4*)(&As[row[r]][c4[r] * 4]) = pa[r];
        *(float4*)(&Bs[row[r]][c4[r] * 4]) = pb[r];
    }
    __syncthreads();

    for (int k0 = 0; k0 < NIN; k0 += BK) {
        bool more = (k0 + BK) < NIN;
        if (more) {
            #pragma unroll
            for (int r = 0; r < 2; r++) {
                pa[r] = *(const float4*)(Ag + (size_t)row[r] * NIN + (k0 + BK) + c4[r] * 4);
                pb[r] = *(const float4*)(Wg + (size_t)row[r] * NIN + (k0 + BK) + c4[r] * 4);
            }
        }
        #pragma unroll
        for (int ks = 0; ks < BK; ks += 8) {
            wmma::fragment<wmma::matrix_a, 16, 16, 8, wmma::precision::tf32, wmma::row_major> af[2];
            wmma::fragment<wmma::matrix_b, 16, 16, 8, wmma::precision::tf32, wmma::col_major> bf[2];
            #pragma unroll
            for (int i = 0; i < 2; i++) {
                wmma::load_matrix_sync(af[i], &As[wm * 32 + i * 16][ks], LDSA);
                #pragma unroll
                for (int t = 0; t < af[i].num_elements; t++) af[i].x[t] = wmma::__float_to_tf32(af[i].x[t]);
            }
            #pragma unroll
            for (int j = 0; j < 2; j++) {
                wmma::load_matrix_sync(bf[j], &Bs[wn * 32 + j * 16][ks], LDSA);
                #pragma unroll
                for (int t = 0; t < bf[j].num_elements; t++) bf[j].x[t] = wmma::__float_to_tf32(bf[j].x[t]);
            }
            #pragma unroll
            for (int i = 0; i < 2; i++)
                #pragma unroll
                for (int j = 0; j < 2; j++)
                    wmma::mma_sync(acc[i][j], af[i], bf[j], acc[i][j]);
        }
        if (more) {
            __syncthreads();
            #pragma unroll
            for (int r = 0; r < 2; r++) {
                *(float4*)(&As[row[r]][c4[r] * 4]) = pa[r];
                *(float4*)(&Bs[row[r]][c4[r] * 4]) = pb[r];
            }
            __syncthreads();
        }
    }
    #pragma unroll
    for (int i = 0; i < 2; i++)
        #pragma unroll
        for (int j = 0; j < 2; j++) {
            float* cp = g_inputs_mul
                      + (size_t)(bm * BM + wm * 32 + i * 16) * TWO_N
                      + bn * BN + wn * 32 + j * 16;
            wmma::store_matrix_sync(cp, acc[i][j], TWO_N, wmma::mem_row_major);
        }
}

// ---------------- complex helpers ----------------
__device__ __forceinline__ float2 cadd(float2 a, float2 b){ return make_float2(a.x+b.x, a.y+b.y); }
__device__ __forceinline__ float2 csub(float2 a, float2 b){ return make_float2(a.x-b.x, a.y-b.y); }
__device__ __forceinline__ float2 cmul(float2 a, float2 b){ return make_float2(a.x*b.x - a.y*b.y, a.x*b.y + a.y*b.x); }
template<bool INV> __device__ __forceinline__ float2 mulj(float2 a){
    return INV ? make_float2(-a.y, a.x) : make_float2(a.y, -a.x);  // *(+i) or *(-i)
}

template<bool INV>
__device__ __forceinline__ void dft4(float2& a0, float2& a1, float2& a2, float2& a3){
    float2 t0 = cadd(a0, a2), t1 = csub(a0, a2);
    float2 t2 = cadd(a1, a3), t3 = mulj<INV>(csub(a1, a3));
    a0 = cadd(t0, t2); a2 = csub(t0, t2);
    a1 = cadd(t1, t3); a3 = csub(t1, t3);
}

template<bool INV>
__device__ __forceinline__ void dft8(float2 x[8]){
    float2 e0=x[0], e1=x[2], e2=x[4], e3=x[6];
    float2 o0=x[1], o1=x[3], o2=x[5], o3=x[7];
    dft4<INV>(e0, e1, e2, e3);
    dft4<INV>(o0, o1, o2, o3);
    const float c8 = 0.70710678118654752f;
    if (!INV) {
        o1 = make_float2(c8*(o1.x + o1.y), c8*(o1.y - o1.x));   // * c8(1-i)
        o2 = make_float2(o2.y, -o2.x);                          // * -i
        o3 = make_float2(c8*(o3.y - o3.x), -c8*(o3.x + o3.y));  // * c8(-1-i)
    } else {
        o1 = make_float2(c8*(o1.x - o1.y), c8*(o1.x + o1.y));   // * c8(1+i)
        o2 = make_float2(-o2.y, o2.x);                          // * +i
        o3 = make_float2(-c8*(o3.x + o3.y), c8*(o3.x - o3.y));  // * c8(-1+i)
    }
    x[0]=cadd(e0,o0); x[4]=csub(e0,o0);
    x[1]=cadd(e1,o1); x[5]=csub(e1,o1);
    x[2]=cadd(e2,o2); x[6]=csub(e2,o2);
    x[3]=cadd(e3,o3); x[7]=csub(e3,o3);
}

// Stockham mixed-radix pass, radix 8, stride S (compile-time). 1 butterfly/thread.
template<bool INV, int S>
__device__ __forceinline__ void pass_r8(const float* __restrict__ sre, const float* __restrict__ sim_,
                                        float* __restrict__ dre, float* __restrict__ dim_,
                                        int tid, const float2* __restrict__ tws){
    float2 x[8];
    #pragma unroll
    for (int k = 0; k < 8; k++) { int i = SW(tid + k * 256); x[k] = make_float2(sre[i], sim_[i]); }
    dft8<INV>(x);
    int ps = tid & ~(S - 1);
    int r  = tid &  (S - 1);
    float2 w1 = tws[ps];
    if (INV) w1.y = -w1.y;
    float2 w = w1;
    #pragma unroll
    for (int k = 1; k < 8; k++) {
        x[k] = cmul(x[k], w);
        if (k < 7) w = cmul(w, w1);
    }
    int base = 8 * ps + r;
    #pragma unroll
    for (int k = 0; k < 8; k++) { int i = SW(base + k * S); dre[i] = x[k].x; dim_[i] = x[k].y; }
}

// Final radix-4 pass, S=512: p==0 -> no twiddle. 2 butterflies/thread.
template<bool INV>
__device__ __forceinline__ void pass_r4f(const float* __restrict__ sre, const float* __restrict__ sim_,
                                         float* __restrict__ dre, float* __restrict__ dim_, int tid){
    #pragma unroll
    for (int t0 = 0; t0 < 2; t0++) {
        int t = tid + t0 * 256;
        float2 a0 = make_float2(sre[SW(t       )], sim_[SW(t       )]);
        float2 a1 = make_float2(sre[SW(t +  512)], sim_[SW(t +  512)]);
        float2 a2 = make_float2(sre[SW(t + 1024)], sim_[SW(t + 1024)]);
        float2 a3 = make_float2(sre[SW(t + 1536)], sim_[SW(t + 1536)]);
        dft4<INV>(a0, a1, a2, a3);
        dre[SW(t       )] = a0.x; dim_[SW(t       )] = a0.y;
        dre[SW(t +  512)] = a1.x; dim_[SW(t +  512)] = a1.y;
        dre[SW(t + 1024)] = a2.x; dim_[SW(t + 1024)] = a2.y;
        dre[SW(t + 1536)] = a3.x; dim_[SW(t + 1536)] = a3.y;
    }
}

// ---------------- per-row pipeline ----------------
__global__ __launch_bounds__(256) void urnn_row_kernel(
    const float* __restrict__ state,
    const float* __restrict__ r1re, const float* __restrict__ r1im,
    const float* __restrict__ r2re, const float* __restrict__ r2im,
    const int*   __restrict__ perm,
    const float* __restrict__ bh,
    float* __restrict__ out) {
    __shared__ float reA[2112], imA[2112], reB[2112], imB[2112];
    __shared__ float2 tws[257];
    __shared__ float2 red[8];
    __shared__ float2 vzsh;

    int tid = threadIdx.x;
    int b   = blockIdx.x;

    // twiddle table from global
    for (int i = tid; i < 257; i += 256) tws[i] = g_tw[i];

    // load state row + diag1
    const float* st = state + (size_t)b * TWO_N;
    #pragma unroll
    for (int k = 0; k < 8; k++) {
        int i = tid + k * 256;
        float re = st[i], im = st[i + N_FFT];
        float2 cs = g_d1cs[i];
        int si = SW(i);
        reA[si] = re * cs.x - im * cs.y;
        imA[si] = re * cs.y + im * cs.x;
    }
    __syncthreads();

    // forward FFT: radices 8,8,8,4
    pass_r8<false, 1 >(reA, imA, reB, imB, tid, tws); __syncthreads();
    pass_r8<false, 8 >(reB, imB, reA, imA, tid, tws); __syncthreads();
    pass_r8<false, 64>(reA, imA, reB, imB, tid, tws); __syncthreads();
    pass_r4f<false>(reB, imB, reA, imA, tid);         __syncthreads();

    unsigned msk = 0xffffffffu;

    // reflect 1 (on A): z and v live in registers across the reduction
    {
        float2 z[8], v[8];
        float2 p = make_float2(0.f, 0.f);
        #pragma unroll
        for (int k = 0; k < 8; k++) {
            int i = tid + k * 256;
            int si = SW(i);
            z[k] = make_float2(reA[si], imA[si]);
            v[k] = make_float2(r1re[i], r1im[i]);
            p.x += z[k].x * v[k].x + z[k].y * v[k].y;   // z * conj(v)
            p.y += z[k].y * v[k].x - z[k].x * v[k].y;
        }
        for (int o = 16; o; o >>= 1) { p.x += __shfl_down_sync(msk, p.x, o); p.y += __shfl_down_sync(msk, p.y, o); }
        if ((tid & 31) == 0) red[tid >> 5] = p;
        __syncthreads();
        if (tid < 32) {
            float2 q = (tid < 8) ? red[tid] : make_float2(0.f, 0.f);
            for (int o = 4; o; o >>= 1) { q.x += __shfl_down_sync(msk, q.x, o); q.y += __shfl_down_sync(msk, q.y, o); }
            if (tid == 0) vzsh = q;
        }
        __syncthreads();
        float2 f = vzsh;
        float fac = g_fac1;
        f.x *= fac; f.y *= fac;
        #pragma unroll
        for (int k = 0; k < 8; k++) {
            int si = SW(tid + k * 256);
            reA[si] = z[k].x - (f.x * v[k].x - f.y * v[k].y);
            imA[si] = z[k].y - (f.x * v[k].y + f.y * v[k].x);
        }
        __syncthreads();
    }

    // permutation + diag2: B[i] = A[perm[i]] * d2[i]
    #pragma unroll
    for (int k = 0; k < 8; k++) {
        int i = tid + k * 256;
        int j = perm[i];
        int sj = SW(j);
        float2 zz = make_float2(reA[sj], imA[sj]);
        float2 cs = g_d2cs[i];
        zz = cmul(zz, cs);
        int si = SW(i);
        reB[si] = zz.x; imB[si] = zz.y;
    }
    __syncthreads();

    // inverse FFT (unnormalized): radices 8,8,8,4 with conjugate twiddles
    pass_r8<true, 1 >(reB, imB, reA, imA, tid, tws); __syncthreads();
    pass_r8<true, 8 >(reA, imA, reB, imB, tid, tws); __syncthreads();
    pass_r8<true, 64>(reB, imB, reA, imA, tid, tws); __syncthreads();
    pass_r4f<true>(reA, imA, reB, imB, tid);         __syncthreads();

    // reflect 2 (on B) fused with diag3 + combine + modReLU epilogue
    {
        float2 z[8], v[8];
        float2 p = make_float2(0.f, 0.f);
        #pragma unroll
        for (int k = 0; k < 8; k++) {
            int i = tid + k * 256;
            int si = SW(i);
            z[k] = make_float2(reB[si], imB[si]);
            v[k] = make_float2(r2re[i], r2im[i]);
            p.x += z[k].x * v[k].x + z[k].y * v[k].y;
            p.y += z[k].y * v[k].x - z[k].x * v[k].y;
        }
        for (int o = 16; o; o >>= 1) { p.x += __shfl_down_sync(msk, p.x, o); p.y += __shfl_down_sync(msk, p.y, o); }
        if ((tid & 31) == 0) red[tid >> 5] = p;
        __syncthreads();
        if (tid < 32) {
            float2 q = (tid < 8) ? red[tid] : make_float2(0.f, 0.f);
            for (int o = 4; o; o >>= 1) { q.x += __shfl_down_sync(msk, q.x, o); q.y += __shfl_down_sync(msk, q.y, o); }
            if (tid == 0) vzsh = q;
        }
        __syncthreads();
        float2 f = vzsh;
        float fac = g_fac2;
        f.x *= fac; f.y *= fac;

        const float* gin = g_inputs_mul + (size_t)b * TWO_N;
        float* ob = out + (size_t)b * TWO_N;
        const float invN = 1.f / (float)N_FFT;
        #pragma unroll
        for (int k = 0; k < 8; k++) {
            int i = tid + k * 256;
            float2 zz;
            zz.x = z[k].x - (f.x * v[k].x - f.y * v[k].y);
            zz.y = z[k].y - (f.x * v[k].y + f.y * v[k].x);
            float2 cs = g_d3cs[i];
            zz = cmul(zz, cs);
            float pre_r = gin[i]         + zz.x * invN;
            float pre_i = gin[i + N_FFT] + zz.y * invN;
            float nrm = sqrtf(pre_r * pre_r + pre_i * pre_i);
            float sc = fmaxf(nrm + bh[i], 0.f) / (nrm + 1e-6f);
            ob[i]         = pre_r * sc;
            ob[i + N_FFT] = pre_i * sc;
        }
    }
}

// ---------------- launch ----------------
extern "C" void kernel_launch(void* const* d_in, const int* in_sizes, int n_in,
                              void* d_out, int out_size) {
    const float* inputs = (const float*)d_in[0];
    const float* state  = (const float*)d_in[1];
    const float* w_ih   = (const float*)d_in[2];
    const float* b_h    = (const float*)d_in[3];
    const float* d1     = (const float*)d_in[4];
    const float* r1re   = (const float*)d_in[5];
    const float* r1im   = (const float*)d_in[6];
    const float* d2     = (const float*)d_in[7];
    const float* r2re   = (const float*)d_in[8];
    const float* r2im   = (const float*)d_in[9];
    const float* d3     = (const float*)d_in[10];
    const int*   perm   = (const int*)d_in[11];
    float* out = (float*)d_out;

    setup_kernel<<<1, 512>>>(d1, r1re, r1im, d2, r2re, r2im, d3);

    dim3 g(TWO_N / BN, BATCH / BM);   // (32, 64)
    gemm_tf32<<<g, 512>>>(inputs, w_ih);

    urnn_row_kernel<<<BATCH, 256>>>(state, r1re, r1im, r2re, r2im, perm, b_h, out);
}

// round 3
// speedup vs baseline: 1.3875x; 1.2378x over previous
#include <cuda_runtime.h>
#include <mma.h>
#include <math.h>

// URNNCell: out = modrelu( complex(inputs@W^T) + D3·R2·IFFT·D2·P·R1·FFT·D1·state_c )
// B=8192, N_IN=1024, N=2048 (complex), 2N=4096.

#define N_FFT   2048
#define BATCH   8192
#define NIN     1024
#define TWO_N   4096
#define SW(i)   ((i) + ((i) >> 5))

using namespace nvcuda;

// ---------------- device scratch ----------------
__device__ float  g_inputs_mul[(size_t)BATCH * TWO_N];
__device__ float2 g_d1cs[N_FFT], g_d2cs[N_FFT], g_d3cs[N_FFT];
__device__ float2 g_tw[257];
__device__ float  g_fac1, g_fac2;

// ---------------- cp.async helpers ----------------
__device__ __forceinline__ void cp_async16(void* smem, const void* gmem) {
    unsigned s = (unsigned)__cvta_generic_to_shared(smem);
    asm volatile("cp.async.cg.shared.global [%0], [%1], 16;\n" :: "r"(s), "l"(gmem));
}
__device__ __forceinline__ void cp_commit() { asm volatile("cp.async.commit_group;\n"); }
template<int N> __device__ __forceinline__ void cp_wait() { asm volatile("cp.async.wait_group %0;\n" :: "n"(N)); }

// ---------------- GEMM (+ fused setup block) ----------------
#define BM 128
#define BN 128
#define BK 32
#define LDSA 36
#define STAGES 3
#define TILE_F (BM * LDSA)              // floats per matrix per stage (4608)
#define GEMM_SMEM (STAGES * 2 * TILE_F * 4)

__device__ void do_setup(const float* __restrict__ d1,
                         const float* __restrict__ r1re, const float* __restrict__ r1im,
                         const float* __restrict__ d2,
                         const float* __restrict__ r2re, const float* __restrict__ r2im,
                         const float* __restrict__ d3, float* sh) {
    int tid = threadIdx.x;   // 256
    float p1 = 0.f, p2 = 0.f;
    for (int i = tid; i < N_FFT; i += 256) {
        float s, c;
        sincosf(d1[i], &s, &c); g_d1cs[i] = make_float2(c, s);
        sincosf(d2[i], &s, &c); g_d2cs[i] = make_float2(c, s);
        sincosf(d3[i], &s, &c); g_d3cs[i] = make_float2(c, s);
        p1 += r1re[i]*r1re[i] + r1im[i]*r1im[i];
        p2 += r2re[i]*r2re[i] + r2im[i]*r2im[i];
    }
    for (int i = tid; i < 257; i += 256) {
        float s, c;
        sincosf(-6.283185307179586f * (float)i / (float)N_FFT, &s, &c);
        g_tw[i] = make_float2(c, s);
    }
    unsigned m = 0xffffffffu;
    for (int o = 16; o; o >>= 1) { p1 += __shfl_down_sync(m, p1, o); p2 += __shfl_down_sync(m, p2, o); }
    int w = tid >> 5, l = tid & 31;
    if (l == 0) { sh[w] = p1; sh[8 + w] = p2; }
    __syncthreads();
    if (w == 0) {
        p1 = (l < 8) ? sh[l] : 0.f;
        p2 = (l < 8) ? sh[8 + l] : 0.f;
        for (int o = 4; o; o >>= 1) { p1 += __shfl_down_sync(m, p1, o); p2 += __shfl_down_sync(m, p2, o); }
        if (l == 0) { g_fac1 = 2.f / p1; g_fac2 = 2.f / p2; }
    }
}

__global__ __launch_bounds__(256) void gemm_tf32(
    const float* __restrict__ A, const float* __restrict__ W,
    const float* __restrict__ d1,
    const float* __restrict__ r1re, const float* __restrict__ r1im,
    const float* __restrict__ d2,
    const float* __restrict__ r2re, const float* __restrict__ r2im,
    const float* __restrict__ d3) {
    extern __shared__ float smem[];

    if (blockIdx.x == (TWO_N / BN)) {            // fused setup column
        if (blockIdx.y == 0) do_setup(d1, r1re, r1im, d2, r2re, r2im, d3, smem);
        return;
    }

    int tid  = threadIdx.x;
    int warp = tid >> 5;
    int wm = warp >> 2;          // 0..1 -> 64-row slab
    int wn = warp & 3;           // 0..3 -> 32-col slab
    int bm = blockIdx.y, bn = blockIdx.x;

    const float* Ag = A + (size_t)bm * BM * NIN;
    const float* Wg = W + (size_t)bn * BN * NIN;

    int row[4], cf[4];
    #pragma unroll
    for (int r = 0; r < 4; r++) { int idx = tid + 256 * r; row[r] = idx >> 3; cf[r] = (idx & 7) * 4; }

    const int NT = NIN / BK;     // 32 k-tiles

    // prologue: stages 0..STAGES-2
    #pragma unroll
    for (int s = 0; s < STAGES - 1; s++) {
        float* As = smem + s * 2 * TILE_F;
        float* Bs = As + TILE_F;
        int k0 = s * BK;
        #pragma unroll
        for (int r = 0; r < 4; r++) {
            cp_async16(&As[row[r] * LDSA + cf[r]], Ag + (size_t)row[r] * NIN + k0 + cf[r]);
            cp_async16(&Bs[row[r] * LDSA + cf[r]], Wg + (size_t)row[r] * NIN + k0 + cf[r]);
        }
        cp_commit();
    }

    wmma::fragment<wmma::accumulator, 16, 16, 8, float> acc[4][2];
    #pragma unroll
    for (int i = 0; i < 4; i++)
        #pragma unroll
        for (int j = 0; j < 2; j++) wmma::fill_fragment(acc[i][j], 0.f);

    for (int t = 0; t < NT; t++) {
        cp_wait<STAGES - 2>();
        __syncthreads();

        // issue loads for tile t+STAGES-1 into stage (t+STAGES-1)%STAGES
        int tn = t + STAGES - 1;
        if (tn < NT) {
            float* As = smem + (tn % STAGES) * 2 * TILE_F;
            float* Bs = As + TILE_F;
            int k0 = tn * BK;
            #pragma unroll
            for (int r = 0; r < 4; r++) {
                cp_async16(&As[row[r] * LDSA + cf[r]], Ag + (size_t)row[r] * NIN + k0 + cf[r]);
                cp_async16(&Bs[row[r] * LDSA + cf[r]], Wg + (size_t)row[r] * NIN + k0 + cf[r]);
            }
        }
        cp_commit();

        float* As = smem + (t % STAGES) * 2 * TILE_F;
        float* Bs = As + TILE_F;
        #pragma unroll
        for (int ks = 0; ks < BK; ks += 8) {
            wmma::fragment<wmma::matrix_a, 16, 16, 8, wmma::precision::tf32, wmma::row_major> af[4];
            wmma::fragment<wmma::matrix_b, 16, 16, 8, wmma::precision::tf32, wmma::col_major> bf[2];
            #pragma unroll
            for (int i = 0; i < 4; i++) {
                wmma::load_matrix_sync(af[i], &As[(wm * 64 + i * 16) * LDSA + ks], LDSA);
                #pragma unroll
                for (int e = 0; e < af[i].num_elements; e++) af[i].x[e] = wmma::__float_to_tf32(af[i].x[e]);
            }
            #pragma unroll
            for (int j = 0; j < 2; j++) {
                wmma::load_matrix_sync(bf[j], &Bs[(wn * 32 + j * 16) * LDSA + ks], LDSA);
                #pragma unroll
                for (int e = 0; e < bf[j].num_elements; e++) bf[j].x[e] = wmma::__float_to_tf32(bf[j].x[e]);
            }
            #pragma unroll
            for (int i = 0; i < 4; i++)
                #pragma unroll
                for (int j = 0; j < 2; j++)
                    wmma::mma_sync(acc[i][j], af[i], bf[j], acc[i][j]);
        }
    }

    #pragma unroll
    for (int i = 0; i < 4; i++)
        #pragma unroll
        for (int j = 0; j < 2; j++) {
            float* cp = g_inputs_mul
                      + (size_t)(bm * BM + wm * 64 + i * 16) * TWO_N
                      + bn * BN + wn * 32 + j * 16;
            wmma::store_matrix_sync(cp, acc[i][j], TWO_N, wmma::mem_row_major);
        }
}

// ---------------- complex helpers ----------------
__device__ __forceinline__ float2 cadd(float2 a, float2 b){ return make_float2(a.x+b.x, a.y+b.y); }
__device__ __forceinline__ float2 csub(float2 a, float2 b){ return make_float2(a.x-b.x, a.y-b.y); }
__device__ __forceinline__ float2 cmul(float2 a, float2 b){ return make_float2(a.x*b.x - a.y*b.y, a.x*b.y + a.y*b.x); }
template<bool INV> __device__ __forceinline__ float2 mulj(float2 a){
    return INV ? make_float2(-a.y, a.x) : make_float2(a.y, -a.x);
}

template<bool INV>
__device__ __forceinline__ void dft4(float2& a0, float2& a1, float2& a2, float2& a3){
    float2 t0 = cadd(a0, a2), t1 = csub(a0, a2);
    float2 t2 = cadd(a1, a3), t3 = mulj<INV>(csub(a1, a3));
    a0 = cadd(t0, t2); a2 = csub(t0, t2);
    a1 = cadd(t1, t3); a3 = csub(t1, t3);
}

template<bool INV>
__device__ __forceinline__ void dft8(float2 x[8]){
    float2 e0=x[0], e1=x[2], e2=x[4], e3=x[6];
    float2 o0=x[1], o1=x[3], o2=x[5], o3=x[7];
    dft4<INV>(e0, e1, e2, e3);
    dft4<INV>(o0, o1, o2, o3);
    const float c8 = 0.70710678118654752f;
    if (!INV) {
        o1 = make_float2(c8*(o1.x + o1.y), c8*(o1.y - o1.x));
        o2 = make_float2(o2.y, -o2.x);
        o3 = make_float2(c8*(o3.y - o3.x), -c8*(o3.x + o3.y));
    } else {
        o1 = make_float2(c8*(o1.x - o1.y), c8*(o1.x + o1.y));
        o2 = make_float2(-o2.y, o2.x);
        o3 = make_float2(-c8*(o3.x + o3.y), c8*(o3.x - o3.y));
    }
    x[0]=cadd(e0,o0); x[4]=csub(e0,o0);
    x[1]=cadd(e1,o1); x[5]=csub(e1,o1);
    x[2]=cadd(e2,o2); x[6]=csub(e2,o2);
    x[3]=cadd(e3,o3); x[7]=csub(e3,o3);
}

template<bool INV, int S>
__device__ __forceinline__ void pass_r8(const float* __restrict__ sre, const float* __restrict__ sim_,
                                        float* __restrict__ dre, float* __restrict__ dim_,
                                        int tid, const float2* __restrict__ tws){
    float2 x[8];
    #pragma unroll
    for (int k = 0; k < 8; k++) { int i = SW(tid + k * 256); x[k] = make_float2(sre[i], sim_[i]); }
    dft8<INV>(x);
    int ps = tid & ~(S - 1);
    int r  = tid &  (S - 1);
    float2 w1 = tws[ps];
    if (INV) w1.y = -w1.y;
    float2 w = w1;
    #pragma unroll
    for (int k = 1; k < 8; k++) {
        x[k] = cmul(x[k], w);
        if (k < 7) w = cmul(w, w1);
    }
    int base = 8 * ps + r;
    #pragma unroll
    for (int k = 0; k < 8; k++) { int i = SW(base + k * S); dre[i] = x[k].x; dim_[i] = x[k].y; }
}

template<bool INV>
__device__ __forceinline__ void pass_r4f(const float* __restrict__ sre, const float* __restrict__ sim_,
                                         float* __restrict__ dre, float* __restrict__ dim_, int tid){
    #pragma unroll
    for (int t0 = 0; t0 < 2; t0++) {
        int t = tid + t0 * 256;
        float2 a0 = make_float2(sre[SW(t       )], sim_[SW(t       )]);
        float2 a1 = make_float2(sre[SW(t +  512)], sim_[SW(t +  512)]);
        float2 a2 = make_float2(sre[SW(t + 1024)], sim_[SW(t + 1024)]);
        float2 a3 = make_float2(sre[SW(t + 1536)], sim_[SW(t + 1536)]);
        dft4<INV>(a0, a1, a2, a3);
        dre[SW(t       )] = a0.x; dim_[SW(t       )] = a0.y;
        dre[SW(t +  512)] = a1.x; dim_[SW(t +  512)] = a1.y;
        dre[SW(t + 1024)] = a2.x; dim_[SW(t + 1024)] = a2.y;
        dre[SW(t + 1536)] = a3.x; dim_[SW(t + 1536)] = a3.y;
    }
}

// ---------------- per-row pipeline ----------------
__global__ __launch_bounds__(256) void urnn_row_kernel(
    const float* __restrict__ state,
    const float* __restrict__ r1re, const float* __restrict__ r1im,
    const float* __restrict__ r2re, const float* __restrict__ r2im,
    const int*   __restrict__ perm,
    const float* __restrict__ bh,
    float* __restrict__ out) {
    __shared__ float reA[2112], imA[2112], reB[2112], imB[2112];
    __shared__ float2 tws[257];
    __shared__ float2 red[8];
    __shared__ float2 vzsh;

    int tid = threadIdx.x;
    int b   = blockIdx.x;
    unsigned msk = 0xffffffffu;

    for (int i = tid; i < 257; i += 256) tws[i] = g_tw[i];

    const float* st = state + (size_t)b * TWO_N;
    #pragma unroll
    for (int k = 0; k < 8; k++) {
        int i = tid + k * 256;
        float re = st[i], im = st[i + N_FFT];
        float2 cs = g_d1cs[i];
        int si = SW(i);
        reA[si] = re * cs.x - im * cs.y;
        imA[si] = re * cs.y + im * cs.x;
    }
    __syncthreads();

    // forward FFT: 8,8,8,4
    pass_r8<false, 1 >(reA, imA, reB, imB, tid, tws); __syncthreads();
    pass_r8<false, 8 >(reB, imB, reA, imA, tid, tws); __syncthreads();
    pass_r8<false, 64>(reA, imA, reB, imB, tid, tws); __syncthreads();
    pass_r4f<false>(reB, imB, reA, imA, tid);         __syncthreads();

    // reflect-1 dot product (no writeback; fused into permutation below)
    {
        float2 p = make_float2(0.f, 0.f);
        #pragma unroll
        for (int k = 0; k < 8; k++) {
            int i = tid + k * 256;
            int si = SW(i);
            float zr = reA[si], zi = imA[si];
            float vr = r1re[i], vi = r1im[i];
            p.x += zr * vr + zi * vi;
            p.y += zi * vr - zr * vi;
        }
        for (int o = 16; o; o >>= 1) { p.x += __shfl_down_sync(msk, p.x, o); p.y += __shfl_down_sync(msk, p.y, o); }
        if ((tid & 31) == 0) red[tid >> 5] = p;
        __syncthreads();
        if (tid < 32) {
            float2 q = (tid < 8) ? red[tid] : make_float2(0.f, 0.f);
            for (int o = 4; o; o >>= 1) { q.x += __shfl_down_sync(msk, q.x, o); q.y += __shfl_down_sync(msk, q.y, o); }
            if (tid == 0) vzsh = q;
        }
        __syncthreads();
    }

    // fused: B[i] = (A[perm[i]] - f*v1[perm[i]]) * d2[i]
    {
        float2 f = vzsh;
        float fac = g_fac1;
        f.x *= fac; f.y *= fac;
        #pragma unroll
        for (int k = 0; k < 8; k++) {
            int i = tid + k * 256;
            int j = perm[i];
            int sj = SW(j);
            float vr = __ldg(r1re + j), vi = __ldg(r1im + j);
            float2 zz;
            zz.x = reA[sj] - (f.x * vr - f.y * vi);
            zz.y = imA[sj] - (f.x * vi + f.y * vr);
            zz = cmul(zz, g_d2cs[i]);
            int si = SW(i);
            reB[si] = zz.x; imB[si] = zz.y;
        }
        __syncthreads();
    }

    // inverse FFT: 8,8,8,4 (conjugate twiddles), unnormalized
    pass_r8<true, 1 >(reB, imB, reA, imA, tid, tws); __syncthreads();
    pass_r8<true, 8 >(reA, imA, reB, imB, tid, tws); __syncthreads();
    pass_r8<true, 64>(reB, imB, reA, imA, tid, tws); __syncthreads();
    pass_r4f<true>(reA, imA, reB, imB, tid);         __syncthreads();

    // reflect-2 fused with diag3 + combine + modReLU epilogue
    {
        float2 z[8], v[8];
        float2 p = make_float2(0.f, 0.f);
        #pragma unroll
        for (int k = 0; k < 8; k++) {
            int i = tid + k * 256;
            int si = SW(i);
            z[k] = make_float2(reB[si], imB[si]);
            v[k] = make_float2(r2re[i], r2im[i]);
            p.x += z[k].x * v[k].x + z[k].y * v[k].y;
            p.y += z[k].y * v[k].x - z[k].x * v[k].y;
        }
        for (int o = 16; o; o >>= 1) { p.x += __shfl_down_sync(msk, p.x, o); p.y += __shfl_down_sync(msk, p.y, o); }
        if ((tid & 31) == 0) red[tid >> 5] = p;
        __syncthreads();
        if (tid < 32) {
            float2 q = (tid < 8) ? red[tid] : make_float2(0.f, 0.f);
            for (int o = 4; o; o >>= 1) { q.x += __shfl_down_sync(msk, q.x, o); q.y += __shfl_down_sync(msk, q.y, o); }
            if (tid == 0) vzsh = q;
        }
        __syncthreads();
        float2 f = vzsh;
        float fac = g_fac2;
        f.x *= fac; f.y *= fac;

        const float* gin = g_inputs_mul + (size_t)b * TWO_N;
        float* ob = out + (size_t)b * TWO_N;
        const float invN = 1.f / (float)N_FFT;
        #pragma unroll
        for (int k = 0; k < 8; k++) {
            int i = tid + k * 256;
            float2 zz;
            zz.x = z[k].x - (f.x * v[k].x - f.y * v[k].y);
            zz.y = z[k].y - (f.x * v[k].y + f.y * v[k].x);
            zz = cmul(zz, g_d3cs[i]);
            float pre_r = gin[i]         + zz.x * invN;
            float pre_i = gin[i + N_FFT] + zz.y * invN;
            float nrm = sqrtf(pre_r * pre_r + pre_i * pre_i);
            float sc = fmaxf(nrm + bh[i], 0.f) / (nrm + 1e-6f);
            ob[i]         = pre_r * sc;
            ob[i + N_FFT] = pre_i * sc;
        }
    }
}

// ---------------- launch ----------------
extern "C" void kernel_launch(void* const* d_in, const int* in_sizes, int n_in,
                              void* d_out, int out_size) {
    const float* inputs = (const float*)d_in[0];
    const float* state  = (const float*)d_in[1];
    const float* w_ih   = (const float*)d_in[2];
    const float* b_h    = (const float*)d_in[3];
    const float* d1     = (const float*)d_in[4];
    const float* r1re   = (const float*)d_in[5];
    const float* r1im   = (const float*)d_in[6];
    const float* d2     = (const float*)d_in[7];
    const float* r2re   = (const float*)d_in[8];
    const float* r2im   = (const float*)d_in[9];
    const float* d3     = (const float*)d_in[10];
    const int*   perm   = (const int*)d_in[11];
    float* out = (float*)d_out;

    static bool attr_done = false;
    if (!attr_done) {
        cudaFuncSetAttribute(gemm_tf32, cudaFuncAttributeMaxDynamicSharedMemorySize, GEMM_SMEM);
        attr_done = true;
    }

    dim3 g(TWO_N / BN + 1, BATCH / BM);   // (33, 64); column 32 = setup block
    gemm_tf32<<<g, 256, GEMM_SMEM>>>(inputs, w_ih, d1, r1re, r1im, d2, r2re, r2im, d3);

    urnn_row_kernel<<<BATCH, 256>>>(state, r1re, r1im, r2re, r2im, perm, b_h, out);
}

// round 5
// speedup vs baseline: 3.5538x; 2.5614x over previous
#include <cuda_runtime.h>
#include <cuda_fp16.h>
#include <math.h>
#include <stdint.h>

// URNNCell: out = modrelu( complex(inputs@W^T) + D3·R2·IFFT·D2·P·R1·FFT·D1·state_c )
// B=8192, N_IN=1024, N=2048 (complex), 2N=4096.

#define N_FFT   2048
#define BATCH   8192
#define NIN     1024
#define TWO_N   4096
#define SW(i)   ((i) + ((i) >> 5))

// ---------------- device scratch ----------------
__device__ float  g_inputs_mul[(size_t)BATCH * TWO_N];
__device__ __half g_Ah[(size_t)BATCH * NIN];
__device__ __half g_Wh[(size_t)TWO_N * NIN];
__device__ float2 g_d1cs[N_FFT], g_d2cs[N_FFT], g_d3cs[N_FFT];
__device__ float2 g_tw[257];
__device__ float  g_fac1, g_fac2;

// ---------------- helpers ----------------
__device__ __forceinline__ uint32_t smem_u32(const void* p) {
    uint32_t a;
    asm("{ .reg .u64 t; cvta.to.shared.u64 t, %1; cvt.u32.u64 %0, t; }" : "=r"(a) : "l"(p));
    return a;
}
__device__ __forceinline__ void cp_async16_s(uint32_t saddr, const void* g) {
    asm volatile("cp.async.cg.shared.global [%0], [%1], 16;\n" :: "r"(saddr), "l"(g));
}
__device__ __forceinline__ void cp_commit() { asm volatile("cp.async.commit_group;\n"); }
template<int N> __device__ __forceinline__ void cp_wait() { asm volatile("cp.async.wait_group %0;\n" :: "n"(N)); }

__device__ __forceinline__ void ldmatrix_x4(uint32_t& r0, uint32_t& r1, uint32_t& r2, uint32_t& r3, uint32_t a) {
    asm volatile("ldmatrix.sync.aligned.m8n8.x4.shared.b16 {%0,%1,%2,%3}, [%4];"
                 : "=r"(r0), "=r"(r1), "=r"(r2), "=r"(r3) : "r"(a));
}
__device__ __forceinline__ void ldmatrix_x2(uint32_t& r0, uint32_t& r1, uint32_t a) {
    asm volatile("ldmatrix.sync.aligned.m8n8.x2.shared.b16 {%0,%1}, [%2];"
                 : "=r"(r0), "=r"(r1) : "r"(a));
}
__device__ __forceinline__ void mma_f16(float& c0, float& c1, float& c2, float& c3,
                                        uint32_t a0, uint32_t a1, uint32_t a2, uint32_t a3,
                                        uint32_t b0, uint32_t b1) {
    asm volatile("mma.sync.aligned.m16n8k16.row.col.f32.f16.f16.f32 "
                 "{%0,%1,%2,%3}, {%4,%5,%6,%7}, {%8,%9}, {%0,%1,%2,%3};"
                 : "+f"(c0), "+f"(c1), "+f"(c2), "+f"(c3)
                 : "r"(a0), "r"(a1), "r"(a2), "r"(a3), "r"(b0), "r"(b1));
}

// ---------------- setup ----------------
__global__ void setup_kernel(const float* __restrict__ d1,
                             const float* __restrict__ r1re, const float* __restrict__ r1im,
                             const float* __restrict__ d2,
                             const float* __restrict__ r2re, const float* __restrict__ r2im,
                             const float* __restrict__ d3) {
    int tid = threadIdx.x;   // 1024
    float p1 = 0.f, p2 = 0.f;
    for (int i = tid; i < N_FFT; i += 1024) {
        float s, c;
        sincosf(d1[i], &s, &c); g_d1cs[i] = make_float2(c, s);
        sincosf(d2[i], &s, &c); g_d2cs[i] = make_float2(c, s);
        sincosf(d3[i], &s, &c); g_d3cs[i] = make_float2(c, s);
        p1 += r1re[i]*r1re[i] + r1im[i]*r1im[i];
        p2 += r2re[i]*r2re[i] + r2im[i]*r2im[i];
    }
    if (tid < 257) {
        float s, c;
        sincosf(-6.283185307179586f * (float)tid / (float)N_FFT, &s, &c);
        g_tw[tid] = make_float2(c, s);
    }
    __shared__ float sh1[32], sh2[32];
    unsigned m = 0xffffffffu;
    for (int o = 16; o; o >>= 1) { p1 += __shfl_down_sync(m, p1, o); p2 += __shfl_down_sync(m, p2, o); }
    int w = tid >> 5, l = tid & 31;
    if (l == 0) { sh1[w] = p1; sh2[w] = p2; }
    __syncthreads();
    if (w == 0) {
        p1 = sh1[l]; p2 = sh2[l];
        for (int o = 16; o; o >>= 1) { p1 += __shfl_down_sync(m, p1, o); p2 += __shfl_down_sync(m, p2, o); }
        if (l == 0) { g_fac1 = 2.f / p1; g_fac2 = 2.f / p2; }
    }
}

// ---------------- fp32 -> fp16 convert (A then W, one grid) ----------------
__global__ __launch_bounds__(256) void convert_kernel(const float* __restrict__ A,
                                                      const float* __restrict__ W) {
    size_t idx = ((size_t)blockIdx.x * 256 + threadIdx.x) * 8;
    const size_t NA = (size_t)BATCH * NIN;               // 8388608
    if (idx < NA) {
        float4 f0 = *(const float4*)(A + idx);
        float4 f1 = *(const float4*)(A + idx + 4);
        __half2* dst = (__half2*)(g_Ah + idx);
        dst[0] = __floats2half2_rn(f0.x, f0.y);
        dst[1] = __floats2half2_rn(f0.z, f0.w);
        dst[2] = __floats2half2_rn(f1.x, f1.y);
        dst[3] = __floats2half2_rn(f1.z, f1.w);
    } else {
        size_t j = idx - NA;
        float4 f0 = *(const float4*)(W + j);
        float4 f1 = *(const float4*)(W + j + 4);
        __half2* dst = (__half2*)(g_Wh + j);
        dst[0] = __floats2half2_rn(f0.x, f0.y);
        dst[1] = __floats2half2_rn(f0.z, f0.w);
        dst[2] = __floats2half2_rn(f1.x, f1.y);
        dst[3] = __floats2half2_rn(f1.z, f1.w);
    }
}

// ---------------- fp16 mma.sync GEMM: C[b,m] = sum_k A[b,k]*W[m,k] ----------------
// CTA tile 128(M) x 128(N), k-chunk 64 (fp16), 3-stage cp.async, 8 warps (warp 64x32).
#define KC 64
#define NCHUNK (NIN / KC)          // 16
#define HSTR 72                    // halves per smem row (64 + 8 pad) = 144B
#define TILE_H (128 * HSTR)        // halves per matrix tile
#define STAGE_H (2 * TILE_H)       // A + B
#define GEMM_SMEM (3 * STAGE_H * 2)  // bytes = 110592... (3*2*9216*2) = 110,592? 

__global__ __launch_bounds__(256) void gemm_f16(int bm_base) {
    extern __shared__ __half hsm[];
    int tid  = threadIdx.x;
    int lane = tid & 31;
    int warp = tid >> 5;
    int wm = warp >> 2;            // 0..1 : 64-row slab
    int wn = warp & 3;             // 0..3 : 32-col slab
    int bm = bm_base + blockIdx.y, bn = blockIdx.x;

    const __half* Ag = g_Ah + (size_t)bm * 128 * NIN;
    const __half* Wg = g_Wh + (size_t)bn * 128 * NIN;

    // cp.async thread mapping: 1024 segs of 16B per tile; 256 thr -> 4 each
    int crow[4], cseg[4];
    #pragma unroll
    for (int r = 0; r < 4; r++) { int idx = tid + 256 * r; crow[r] = idx >> 3; cseg[r] = idx & 7; }

    uint32_t sbase = smem_u32(hsm);

    // prologue: chunks 0,1 into stages 0,1
    #pragma unroll
    for (int s = 0; s < 2; s++) {
        uint32_t stA = sbase + s * STAGE_H * 2;
        uint32_t stB = stA + TILE_H * 2;
        int k0 = s * KC;
        #pragma unroll
        for (int r = 0; r < 4; r++) {
            cp_async16_s(stA + (crow[r] * HSTR + cseg[r] * 8) * 2, Ag + (size_t)crow[r] * NIN + k0 + cseg[r] * 8);
            cp_async16_s(stB + (crow[r] * HSTR + cseg[r] * 8) * 2, Wg + (size_t)crow[r] * NIN + k0 + cseg[r] * 8);
        }
        cp_commit();
    }

    float acc[4][4][4];   // [m16 tile][n8 tile][reg]
    #pragma unroll
    for (int i = 0; i < 4; i++)
        #pragma unroll
        for (int j = 0; j < 4; j++)
            #pragma unroll
            for (int q = 0; q < 4; q++) acc[i][j][q] = 0.f;

    // ldmatrix per-lane offsets (halves)
    int a_row = wm * 64 + (lane & 15);          // + mi*16
    int a_koff = (lane >> 4) * 8;               // 0 or 8
    int b_row = wn * 32 + (lane & 7);           // + ni*8  (lanes 0..15 used)
    int b_koff = ((lane >> 3) & 1) * 8;

    for (int t = 0; t < NCHUNK; t++) {
        cp_wait<1>();
        __syncthreads();
        if (t + 2 < NCHUNK) {
            uint32_t stA = sbase + ((t + 2) % 3) * STAGE_H * 2;
            uint32_t stB = stA + TILE_H * 2;
            int k0 = (t + 2) * KC;
            #pragma unroll
            for (int r = 0; r < 4; r++) {
                cp_async16_s(stA + (crow[r] * HSTR + cseg[r] * 8) * 2, Ag + (size_t)crow[r] * NIN + k0 + cseg[r] * 8);
                cp_async16_s(stB + (crow[r] * HSTR + cseg[r] * 8) * 2, Wg + (size_t)crow[r] * NIN + k0 + cseg[r] * 8);
            }
        }
        cp_commit();

        uint32_t stA = sbase + (t % 3) * STAGE_H * 2;
        uint32_t stB = stA + TILE_H * 2;
        #pragma unroll
        for (int ks = 0; ks < KC; ks += 16) {
            uint32_t af[4][4], bf[4][2];
            #pragma unroll
            for (int i = 0; i < 4; i++)
                ldmatrix_x4(af[i][0], af[i][1], af[i][2], af[i][3],
                            stA + ((a_row + i * 16) * HSTR + ks + a_koff) * 2);
            #pragma unroll
            for (int j = 0; j < 4; j++)
                ldmatrix_x2(bf[j][0], bf[j][1],
                            stB + ((b_row + j * 8) * HSTR + ks + b_koff) * 2);
            #pragma unroll
            for (int i = 0; i < 4; i++)
                #pragma unroll
                for (int j = 0; j < 4; j++)
                    mma_f16(acc[i][j][0], acc[i][j][1], acc[i][j][2], acc[i][j][3],
                            af[i][0], af[i][1], af[i][2], af[i][3], bf[j][0], bf[j][1]);
        }
        __syncthreads();
    }

    // epilogue: acc layout c0,c1 -> row lane/4, cols 2*(lane%4); c2,c3 -> row+8
    {
        int r0 = lane >> 2, cc = (lane & 3) * 2;
        #pragma unroll
        for (int i = 0; i < 4; i++) {
            size_t rowg0 = (size_t)(bm * 128 + wm * 64 + i * 16 + r0) * TWO_N;
            size_t rowg1 = rowg0 + 8 * TWO_N;
            #pragma unroll
            for (int j = 0; j < 4; j++) {
                int col = bn * 128 + wn * 32 + j * 8 + cc;
                *(float2*)(g_inputs_mul + rowg0 + col) = make_float2(acc[i][j][0], acc[i][j][1]);
                *(float2*)(g_inputs_mul + rowg1 + col) = make_float2(acc[i][j][2], acc[i][j][3]);
            }
        }
    }
}

// ---------------- complex helpers ----------------
__device__ __forceinline__ float2 cadd(float2 a, float2 b){ return make_float2(a.x+b.x, a.y+b.y); }
__device__ __forceinline__ float2 csub(float2 a, float2 b){ return make_float2(a.x-b.x, a.y-b.y); }
__device__ __forceinline__ float2 cmul(float2 a, float2 b){ return make_float2(a.x*b.x - a.y*b.y, a.x*b.y + a.y*b.x); }
template<bool INV> __device__ __forceinline__ float2 mulj(float2 a){
    return INV ? make_float2(-a.y, a.x) : make_float2(a.y, -a.x);
}

template<bool INV>
__device__ __forceinline__ void dft4(float2& a0, float2& a1, float2& a2, float2& a3){
    float2 t0 = cadd(a0, a2), t1 = csub(a0, a2);
    float2 t2 = cadd(a1, a3), t3 = mulj<INV>(csub(a1, a3));
    a0 = cadd(t0, t2); a2 = csub(t0, t2);
    a1 = cadd(t1, t3); a3 = csub(t1, t3);
}

template<bool INV>
__device__ __forceinline__ void dft8(float2 x[8]){
    float2 e0=x[0], e1=x[2], e2=x[4], e3=x[6];
    float2 o0=x[1], o1=x[3], o2=x[5], o3=x[7];
    dft4<INV>(e0, e1, e2, e3);
    dft4<INV>(o0, o1, o2, o3);
    const float c8 = 0.70710678118654752f;
    if (!INV) {
        o1 = make_float2(c8*(o1.x + o1.y), c8*(o1.y - o1.x));
        o2 = make_float2(o2.y, -o2.x);
        o3 = make_float2(c8*(o3.y - o3.x), -c8*(o3.x + o3.y));
    } else {
        o1 = make_float2(c8*(o1.x - o1.y), c8*(o1.x + o1.y));
        o2 = make_float2(-o2.y, o2.x);
        o3 = make_float2(-c8*(o3.x + o3.y), c8*(o3.x - o3.y));
    }
    x[0]=cadd(e0,o0); x[4]=csub(e0,o0);
    x[1]=cadd(e1,o1); x[5]=csub(e1,o1);
    x[2]=cadd(e2,o2); x[6]=csub(e2,o2);
    x[3]=cadd(e3,o3); x[7]=csub(e3,o3);
}

template<bool INV, int S>
__device__ __forceinline__ void pass_r8(const float* __restrict__ sre, const float* __restrict__ sim_,
                                        float* __restrict__ dre, float* __restrict__ dim_,
                                        int tid, const float2* __restrict__ tws){
    float2 x[8];
    #pragma unroll
    for (int k = 0; k < 8; k++) { int i = SW(tid + k * 256); x[k] = make_float2(sre[i], sim_[i]); }
    dft8<INV>(x);
    int ps = tid & ~(S - 1);
    int r  = tid &  (S - 1);
    float2 w1 = tws[ps];
    if (INV) w1.y = -w1.y;
    float2 w = w1;
    #pragma unroll
    for (int k = 1; k < 8; k++) {
        x[k] = cmul(x[k], w);
        if (k < 7) w = cmul(w, w1);
    }
    int base = 8 * ps + r;
    #pragma unroll
    for (int k = 0; k < 8; k++) { int i = SW(base + k * S); dre[i] = x[k].x; dim_[i] = x[k].y; }
}

template<bool INV>
__device__ __forceinline__ void pass_r4f(const float* __restrict__ sre, const float* __restrict__ sim_,
                                         float* __restrict__ dre, float* __restrict__ dim_, int tid){
    #pragma unroll
    for (int t0 = 0; t0 < 2; t0++) {
        int t = tid + t0 * 256;
        float2 a0 = make_float2(sre[SW(t       )], sim_[SW(t       )]);
        float2 a1 = make_float2(sre[SW(t +  512)], sim_[SW(t +  512)]);
        float2 a2 = make_float2(sre[SW(t + 1024)], sim_[SW(t + 1024)]);
        float2 a3 = make_float2(sre[SW(t + 1536)], sim_[SW(t + 1536)]);
        dft4<INV>(a0, a1, a2, a3);
        dre[SW(t       )] = a0.x; dim_[SW(t       )] = a0.y;
        dre[SW(t +  512)] = a1.x; dim_[SW(t +  512)] = a1.y;
        dre[SW(t + 1024)] = a2.x; dim_[SW(t + 1024)] = a2.y;
        dre[SW(t + 1536)] = a3.x; dim_[SW(t + 1536)] = a3.y;
    }
}

// ---------------- per-row pipeline ----------------
__global__ __launch_bounds__(256) void urnn_row_kernel(
    const float* __restrict__ state,
    const float* __restrict__ r1re, const float* __restrict__ r1im,
    const float* __restrict__ r2re, const float* __restrict__ r2im,
    const int*   __restrict__ perm,
    const float* __restrict__ bh,
    float* __restrict__ out) {
    __shared__ float reA[2112], imA[2112], reB[2112], imB[2112];
    __shared__ float2 tws[257];
    __shared__ float2 red[8];
    __shared__ float2 vzsh;

    int tid = threadIdx.x;
    int b   = blockIdx.x;
    unsigned msk = 0xffffffffu;

    for (int i = tid; i < 257; i += 256) tws[i] = g_tw[i];

    const float* st = state + (size_t)b * TWO_N;
    #pragma unroll
    for (int k = 0; k < 8; k++) {
        int i = tid + k * 256;
        float re = st[i], im = st[i + N_FFT];
        float2 cs = g_d1cs[i];
        int si = SW(i);
        reA[si] = re * cs.x - im * cs.y;
        imA[si] = re * cs.y + im * cs.x;
    }
    __syncthreads();

    pass_r8<false, 1 >(reA, imA, reB, imB, tid, tws); __syncthreads();
    pass_r8<false, 8 >(reB, imB, reA, imA, tid, tws); __syncthreads();
    pass_r8<false, 64>(reA, imA, reB, imB, tid, tws); __syncthreads();
    pass_r4f<false>(reB, imB, reA, imA, tid);         __syncthreads();

    {   // reflect-1 dot product (writeback fused into permutation)
        float2 p = make_float2(0.f, 0.f);
        #pragma unroll
        for (int k = 0; k < 8; k++) {
            int i = tid + k * 256;
            int si = SW(i);
            float zr = reA[si], zi = imA[si];
            float vr = r1re[i], vi = r1im[i];
            p.x += zr * vr + zi * vi;
            p.y += zi * vr - zr * vi;
        }
        for (int o = 16; o; o >>= 1) { p.x += __shfl_down_sync(msk, p.x, o); p.y += __shfl_down_sync(msk, p.y, o); }
        if ((tid & 31) == 0) red[tid >> 5] = p;
        __syncthreads();
        if (tid < 32) {
            float2 q = (tid < 8) ? red[tid] : make_float2(0.f, 0.f);
            for (int o = 4; o; o >>= 1) { q.x += __shfl_down_sync(msk, q.x, o); q.y += __shfl_down_sync(msk, q.y, o); }
            if (tid == 0) vzsh = q;
        }
        __syncthreads();
    }

    {   // B[i] = (A[perm[i]] - f*v1[perm[i]]) * d2[i]
        float2 f = vzsh;
        float fac = g_fac1;
        f.x *= fac; f.y *= fac;
        #pragma unroll
        for (int k = 0; k < 8; k++) {
            int i = tid + k * 256;
            int j = perm[i];
            int sj = SW(j);
            float vr = __ldg(r1re + j), vi = __ldg(r1im + j);
            float2 zz;
            zz.x = reA[sj] - (f.x * vr - f.y * vi);
            zz.y = imA[sj] - (f.x * vi + f.y * vr);
            zz = cmul(zz, g_d2cs[i]);
            int si = SW(i);
            reB[si] = zz.x; imB[si] = zz.y;
        }
        __syncthreads();
    }

    pass_r8<true, 1 >(reB, imB, reA, imA, tid, tws); __syncthreads();
    pass_r8<true, 8 >(reA, imA, reB, imB, tid, tws); __syncthreads();
    pass_r8<true, 64>(reB, imB, reA, imA, tid, tws); __syncthreads();
    pass_r4f<true>(reA, imA, reB, imB, tid);         __syncthreads();

    {   // reflect-2 + diag3 + combine + modReLU
        float2 z[8], v[8];
        float2 p = make_float2(0.f, 0.f);
        #pragma unroll
        for (int k = 0; k < 8; k++) {
            int i = tid + k * 256;
            int si = SW(i);
            z[k] = make_float2(reB[si], imB[si]);
            v[k] = make_float2(r2re[i], r2im[i]);
            p.x += z[k].x * v[k].x + z[k].y * v[k].y;
            p.y += z[k].y * v[k].x - z[k].x * v[k].y;
        }
        for (int o = 16; o; o >>= 1) { p.x += __shfl_down_sync(msk, p.x, o); p.y += __shfl_down_sync(msk, p.y, o); }
        if ((tid & 31) == 0) red[tid >> 5] = p;
        __syncthreads();
        if (tid < 32) {
            float2 q = (tid < 8) ? red[tid] : make_float2(0.f, 0.f);
            for (int o = 4; o; o >>= 1) { q.x += __shfl_down_sync(msk, q.x, o); q.y += __shfl_down_sync(msk, q.y, o); }
            if (tid == 0) vzsh = q;
        }
        __syncthreads();
        float2 f = vzsh;
        float fac = g_fac2;
        f.x *= fac; f.y *= fac;

        const float* gin = g_inputs_mul + (size_t)b * TWO_N;
        float* ob = out + (size_t)b * TWO_N;
        const float invN = 1.f / (float)N_FFT;
        #pragma unroll
        for (int k = 0; k < 8; k++) {
            int i = tid + k * 256;
            float2 zz;
            zz.x = z[k].x - (f.x * v[k].x - f.y * v[k].y);
            zz.y = z[k].y - (f.x * v[k].y + f.y * v[k].x);
            zz = cmul(zz, g_d3cs[i]);
            float pre_r = gin[i]         + zz.x * invN;
            float pre_i = gin[i + N_FFT] + zz.y * invN;
            float nrm = sqrtf(pre_r * pre_r + pre_i * pre_i);
            float sc = fmaxf(nrm + bh[i], 0.f) / (nrm + 1e-6f);
            ob[i]         = pre_r * sc;
            ob[i + N_FFT] = pre_i * sc;
        }
    }
}

// ---------------- launch ----------------
extern "C" void kernel_launch(void* const* d_in, const int* in_sizes, int n_in,
                              void* d_out, int out_size) {
    const float* inputs = (const float*)d_in[0];
    const float* state  = (const float*)d_in[1];
    const float* w_ih   = (const float*)d_in[2];
    const float* b_h    = (const float*)d_in[3];
    const float* d1     = (const float*)d_in[4];
    const float* r1re   = (const float*)d_in[5];
    const float* r1im   = (const float*)d_in[6];
    const float* d2     = (const float*)d_in[7];
    const float* r2re   = (const float*)d_in[8];
    const float* r2im   = (const float*)d_in[9];
    const float* d3     = (const float*)d_in[10];
    const int*   perm   = (const int*)d_in[11];
    float* out = (float*)d_out;

    static bool attr_done = false;
    if (!attr_done) {
        cudaFuncSetAttribute(gemm_f16, cudaFuncAttributeMaxDynamicSharedMemorySize, GEMM_SMEM);
        attr_done = true;
    }

    setup_kernel<<<1, 1024>>>(d1, r1re, r1im, d2, r2re, r2im, d3);

    // convert A (8192x1024) + W (4096x1024) to fp16: 12.58M elems / 2048 per block
    convert_kernel<<<(int)(((size_t)BATCH * NIN + (size_t)TWO_N * NIN) / 2048), 256>>>(inputs, w_ih);

    dim3 gg(TWO_N / 128, BATCH / 128);    // (32, 64)
    gemm_f16<<<gg, 256, GEMM_SMEM>>>(0);

    urnn_row_kernel<<<BATCH, 256>>>(state, r1re, r1im, r2re, r2im, perm, b_h, out);
}